// round 2
// baseline (speedup 1.0000x reference)
#include <cuda_runtime.h>

#define TLEN 4096
#define DDIM 1024

__device__ __forceinline__ float sigm(float v) { return 1.0f / (1.0f + expf(-v)); }

__global__ void __launch_bounds__(256)
clifford_kernel(const float* __restrict__ x,
                const float* __restrict__ gate_w,
                const float* __restrict__ gate_b,
                const float* __restrict__ sw,
                const float* __restrict__ bw,
                float* __restrict__ out)
{
    const int tid   = threadIdx.x;
    const int rib   = tid >> 6;        // row in block: 0..3
    const int chunk = tid & 63;        // 0..63 (16 floats each)
    const long long row   = (long long)blockIdx.x * 4 + rib;   // 0..B*T-1
    const int       t     = (int)(row & (TLEN - 1));
    const long long base  = row * DDIM + chunk * 16;
    const long long brow0 = (row - t) * DDIM;                  // batch start

    // x chunk (16 floats)
    float4 X0 = __ldg((const float4*)(x + base));
    float4 X1 = __ldg((const float4*)(x + base + 4));
    float4 X2 = __ldg((const float4*)(x + base + 8));
    float4 X3 = __ldg((const float4*)(x + base + 12));

    // gate partial dot: x . gate_w over this chunk
    const float4 W0 = __ldg((const float4*)(gate_w + chunk * 16));
    const float4 W1 = __ldg((const float4*)(gate_w + chunk * 16 + 4));
    const float4 W2 = __ldg((const float4*)(gate_w + chunk * 16 + 8));
    const float4 W3 = __ldg((const float4*)(gate_w + chunk * 16 + 12));
    float gsum = X0.x*W0.x + X0.y*W0.y + X0.z*W0.z + X0.w*W0.w
               + X1.x*W1.x + X1.y*W1.y + X1.z*W1.z + X1.w*W1.w
               + X2.x*W2.x + X2.y*W2.y + X2.z*W2.z + X2.w*W2.w
               + X3.x*W3.x + X3.y*W3.y + X3.z*W3.z + X3.w*W3.w;

    float sc = 0.f;                       // signed scalar-part partial
    float b3 = 0.f, b5 = 0.f, b6 = 0.f, b9 = 0.f, b10 = 0.f, b12 = 0.f;

    #pragma unroll
    for (int si = 0; si < 3; si++) {
        const int shift = 1 << si;        // 1,2,4
        const int tp = (t - shift) & (TLEN - 1);
        const float* p = x + brow0 + (long long)tp * DDIM + chunk * 16;
        const float4 P0 = __ldg((const float4*)(p));
        const float4 P1 = __ldg((const float4*)(p + 4));
        const float4 P2 = __ldg((const float4*)(p + 8));
        const float4 P3 = __ldg((const float4*)(p + 12));

        // c = x - roll(x, shift)
        const float c00 = X0.x - P0.x, c01 = X0.y - P0.y, c02 = X0.z - P0.z, c03 = X0.w - P0.w;
        const float c10 = X1.x - P1.x, c11 = X1.y - P1.y, c12 = X1.z - P1.z, c13 = X1.w - P1.w;
        const float c20 = X2.x - P2.x, c21 = X2.y - P2.y, c22 = X2.z - P2.z, c23 = X2.w - P2.w;
        const float c30 = X3.x - P3.x, c31 = X3.y - P3.y, c32 = X3.z - P3.z, c33 = X3.w - P3.w;

        // scalar part: sgn per blade idx
        // idx 0..15: +,+,+,-, +,-,-,-, -,+,+,+, +,+,+,-
        sc += X0.x*c00 + X0.y*c01 + X0.z*c02 - X0.w*c03;
        sc += X1.x*c10 - X1.y*c11 - X1.z*c12 - X1.w*c13;
        sc += -X2.x*c20 + X2.y*c21 + X2.z*c22 + X2.w*c23;
        sc += X3.x*c30 + X3.y*c31 + X3.z*c32 - X3.w*c33;

        // wedge of vector parts: vec idx 1,2,4,8 -> x1=X0.y, x2=X0.z, x4=X1.x, x8=X2.x
        b3  += X0.y*c02 - X0.z*c01;   // e0^e1  (blade 3)
        b5  += X0.y*c10 - X1.x*c01;   // e0^e2  (blade 5)
        b6  += X0.z*c10 - X1.x*c02;   // e1^e2  (blade 6)
        b9  += X0.y*c20 - X2.x*c01;   // e0^e3  (blade 9)
        b10 += X0.z*c20 - X2.x*c02;   // e1^e3  (blade 10)
        b12 += X1.x*c20 - X2.x*c10;   // e2^e3  (blade 12)
    }

    // reduce gsum and sc across the 64 threads of this row (2 warps)
    #pragma unroll
    for (int o = 16; o > 0; o >>= 1) {
        gsum += __shfl_xor_sync(0xffffffffu, gsum, o);
        sc   += __shfl_xor_sync(0xffffffffu, sc, o);
    }
    __shared__ float s_g[8], s_s[8];
    const int wid = tid >> 5;
    if ((tid & 31) == 0) { s_g[wid] = gsum; s_s[wid] = sc; }
    __syncthreads();

    const float gate = sigm(s_g[2 * rib] + s_g[2 * rib + 1] + __ldg(gate_b));
    const float sct  = s_s[2 * rib] + s_s[2 * rib + 1];
    const float gss  = gate * sigm(__ldg(sw));   // gate * sigmoid(scalar_weight)
    const float gsb  = gate * sigm(__ldg(bw));   // gate * sigmoid(bivector_weight)

    // out = x + gate * delta  (bivector lanes + scalar at d==0)
    X0.w += gsb * b3;
    X1.y += gsb * b5;
    X1.z += gsb * b6;
    X2.y += gsb * b9;
    X2.z += gsb * b10;
    X3.x += gsb * b12;
    if (chunk == 0) X0.x += gss * sct;

    float4* o4 = (float4*)(out + base);
    o4[0] = X0; o4[1] = X1; o4[2] = X2; o4[3] = X3;
}

extern "C" void kernel_launch(void* const* d_in, const int* in_sizes, int n_in,
                              void* d_out, int out_size)
{
    const float* x  = (const float*)d_in[0];
    const float* gw = (const float*)d_in[1];
    const float* gb = (const float*)d_in[2];
    const float* sw = (const float*)d_in[3];
    const float* bw = (const float*)d_in[4];
    float* out = (float*)d_out;

    const int rows = in_sizes[0] / DDIM;   // B*T = 32768
    clifford_kernel<<<rows / 4, 256>>>(x, gw, gb, sw, bw, out);
}

// round 4
// speedup vs baseline: 1.6461x; 1.6461x over previous
#include <cuda_runtime.h>

#define TLEN 4096
#define DDIM 1024
#define STEPS 16

__device__ __forceinline__ float sigm(float v) { return 1.0f / (1.0f + expf(-v)); }

__global__ void __launch_bounds__(256, 2)
clifford_ring_kernel(const float* __restrict__ x,
                     const float* __restrict__ gate_w,
                     const float* __restrict__ gate_b,
                     const float* __restrict__ sw,
                     const float* __restrict__ bw,
                     float* __restrict__ out)
{
    const int l = threadIdx.x;          // lane over D/4 = 256 float4 slots
    const int q = l & 3;                // quarter within a 16-float chunk
    const int tb_per_b = TLEN / STEPS;  // 256
    const int b  = blockIdx.x / tb_per_b;
    const int t0 = (blockIdx.x % tb_per_b) * STEPS;

    const float* xb = x   + (long long)b * TLEN * DDIM + 4 * l;
    float*       ob = out + (long long)b * TLEN * DDIM + 4 * l;

    const float4 W  = __ldg((const float4*)(gate_w + 4 * l));
    const float gb0 = __ldg(gate_b);
    const float ssc = sigm(__ldg(sw));   // sigmoid(scalar_weight)
    const float sbc = sigm(__ldg(bw));   // sigmoid(bivector_weight)

    // signed-metric sign vector for the grade-0 (scalar) contraction, per quarter
    // blade idx 0..15 signs: +,+,+,-  +,-,-,-  -,+,+,+  +,+,+,-
    float4 sg;
    if      (q == 0) sg = make_float4( 1.f,  1.f,  1.f, -1.f);
    else if (q == 1) sg = make_float4( 1.f, -1.f, -1.f, -1.f);
    else if (q == 2) sg = make_float4(-1.f,  1.f,  1.f,  1.f);
    else             sg = make_float4( 1.f,  1.f,  1.f, -1.f);

    __shared__ float2 red[2][8];

    float4 ring[8];
    // prologue: rows t0-4 .. t0 (wrapped)
    #pragma unroll
    for (int j = -4; j <= 0; j++) {
        const int a = (t0 + j) & (TLEN - 1);
        ring[j & 7] = __ldg((const float4*)(xb + (long long)a * DDIM));
    }

    const unsigned FULL = 0xffffffffu;

    #pragma unroll
    for (int k = 1; k <= STEPS; k++) {
        // prefetch next row (one step ahead of its use)
        if (k < STEPS)
            ring[k & 7] = __ldg((const float4*)(xb + (long long)(t0 + k) * DDIM));

        const int r = t0 + k - 1;                 // row being computed
        const float4 X  = ring[(k - 1) & 7];
        const float4 M1 = ring[(k - 2) & 7];
        const float4 M2 = ring[(k - 3) & 7];
        const float4 M4 = ring[(k - 5) & 7];

        // S = x_{t-1} + x_{t-2} + x_{t-4}
        const float4 S = make_float4(M1.x + M2.x + M4.x,
                                     M1.y + M2.y + M4.y,
                                     M1.z + M2.z + M4.z,
                                     M1.w + M2.w + M4.w);

        // gate partial: x . gate_w
        float g = X.x * W.x + X.y * W.y + X.z * W.z + X.w * W.w;

        // scalar partial: sum over shifts of <x, x - x_s>_signed = <x, 3x - S>_signed
        const float4 tt = make_float4(3.f * X.x - S.x, 3.f * X.y - S.y,
                                      3.f * X.z - S.z, 3.f * X.w - S.w);
        float sc = sg.x * X.x * tt.x + sg.y * X.y * tt.y
                 + sg.z * X.z * tt.z + sg.w * X.w * tt.w;

        // wedge over shifts: x^(3x - S) = -(x^S)  => b_pq = x_q*S_p - x_p*S_q
        // vector blades within chunk: x1=q0.y, x2=q0.z, x4=q1.x, x8=q2.x
        const float x1v = __shfl_sync(FULL, X.y, 0, 4);
        const float x2v = __shfl_sync(FULL, X.z, 0, 4);
        const float x4v = __shfl_sync(FULL, X.x, 1, 4);
        const float x8v = __shfl_sync(FULL, X.x, 2, 4);
        const float S1v = __shfl_sync(FULL, S.y, 0, 4);
        const float S2v = __shfl_sync(FULL, S.z, 0, 4);
        const float S4v = __shfl_sync(FULL, S.x, 1, 4);
        const float S8v = __shfl_sync(FULL, S.x, 2, 4);

        const float b3  = x2v * S1v - x1v * S2v;   // e0^e1 -> blade 3  (q0.w)
        const float b5  = x4v * S1v - x1v * S4v;   // e0^e2 -> blade 5  (q1.y)
        const float b6  = x4v * S2v - x2v * S4v;   // e1^e2 -> blade 6  (q1.z)
        const float b9  = x8v * S1v - x1v * S8v;   // e0^e3 -> blade 9  (q2.y)
        const float b10 = x8v * S2v - x2v * S8v;   // e1^e3 -> blade 10 (q2.z)
        const float b12 = x8v * S4v - x4v * S8v;   // e2^e3 -> blade 12 (q3.x)

        // block-wide reduce of g and sc
        #pragma unroll
        for (int o = 16; o > 0; o >>= 1) {
            g  += __shfl_xor_sync(FULL, g,  o);
            sc += __shfl_xor_sync(FULL, sc, o);
        }
        const int buf = k & 1;
        if ((l & 31) == 0) red[buf][l >> 5] = make_float2(g, sc);
        __syncthreads();
        float G = 0.f, SC = 0.f;
        #pragma unroll
        for (int w = 0; w < 8; w++) { G += red[buf][w].x; SC += red[buf][w].y; }

        const float gate = 1.f / (1.f + __expf(-(G + gb0)));
        const float gss  = gate * ssc;
        const float gsb  = gate * sbc;

        float4 O = X;
        O.x += (q == 3) ? gsb * b12 : ((l == 0) ? gss * SC : 0.f);
        O.y += (q == 1) ? gsb * b5  : ((q == 2) ? gsb * b9  : 0.f);
        O.z += (q == 1) ? gsb * b6  : ((q == 2) ? gsb * b10 : 0.f);
        O.w += (q == 0) ? gsb * b3  : 0.f;

        *(float4*)(ob + (long long)r * DDIM) = O;
    }
}

extern "C" void kernel_launch(void* const* d_in, const int* in_sizes, int n_in,
                              void* d_out, int out_size)
{
    const float* x  = (const float*)d_in[0];
    const float* gw = (const float*)d_in[1];
    const float* gb = (const float*)d_in[2];
    const float* sw = (const float*)d_in[3];
    const float* bw = (const float*)d_in[4];
    float* out = (float*)d_out;

    const int rows = in_sizes[0] / DDIM;        // B*T
    clifford_ring_kernel<<<rows / STEPS, 256>>>(x, gw, gb, sw, bw, out);
}